// round 15
// baseline (speedup 1.0000x reference)
#include <cuda_runtime.h>
#include <cuda_bf16.h>
#include <cstdint>

// Problem constants
#define MAX_N     512
#define N_CLASSES 64
#define MESH_DIM  128
#define NUM_CLUT  5
#define BANK_SIZE 4096
#define BATCH     4
#define FEAT_ROWS (MAX_N + NUM_CLUT)          // 517
#define CJ        (N_CLASSES * MAX_N)          // 32768
#define NCLUT_TOT (NUM_CLUT * BANK_SIZE)       // 20480
#define NTOT      (CJ + NCLUT_TOT)             // 53248
#define M_TOT     (BATCH * MAX_N)              // 2048
#define NB_INS    (NUM_CLUT * BATCH)           // 20 inserted columns

// Output offsets (element counts)
#define OUT_SIM_OFF   0ULL
#define OUT_SIM_SZ    ((unsigned long long)BATCH * MAX_N * NTOT)
#define OUT_NSIM_OFF  (OUT_SIM_OFF + OUT_SIM_SZ)
#define OUT_NSIM_SZ   ((unsigned long long)BATCH * NUM_CLUT * CJ)
#define OUT_MEM_OFF   (OUT_NSIM_OFF + OUT_NSIM_SZ)
#define OUT_MEM_SZ    ((unsigned long long)N_CLASSES * MESH_DIM * MAX_N)
#define OUT_CB_OFF    (OUT_MEM_OFF + OUT_MEM_SZ)

// ---------------------------------------------------------------------------
// tf32 A scratch (device global — allocation-free rule).
// Row-major [m][k], k permuted within 8-blocks: pos 2t,2t+1 hold k=t,t+4
// so fragment pairs (k, k+4) are one LDS.64.
// ---------------------------------------------------------------------------
__device__ __align__(16) float g_A[(size_t)M_TOT * MESH_DIM];   // 1 MB

__device__ __forceinline__ int kpos(int k) {
    return (k & ~7) | (((k & 3) << 1) | ((k >> 2) & 1));
}

__device__ __forceinline__ float to_tf32(float x) {
    uint32_t u;
    asm("cvt.rna.tf32.f32 %0, %1;" : "=r"(u) : "f"(x));
    return __uint_as_float(u);
}

__device__ __forceinline__ uint32_t smem_u32(const void* p) {
    uint32_t a;
    asm("{ .reg .u64 t; cvta.to.shared.u64 t, %1; cvt.u32.u64 %0, t; }" : "=r"(a) : "l"(p));
    return a;
}

#define CP_ASYNC16(saddr, gptr) \
    asm volatile("cp.async.cg.shared.global [%0], [%1], 16;" :: "r"(saddr), "l"(gptr))
#define CP_COMMIT() asm volatile("cp.async.commit_group;")
#define CP_WAIT0()  asm volatile("cp.async.wait_group 0;")

// m16n8k8 tf32 MMA (sm_80 baseline — works at compute_103)
__device__ __forceinline__ void mma_tf32(float& c0, float& c1, float& c2, float& c3,
                                         uint32_t a0, uint32_t a1, uint32_t a2, uint32_t a3,
                                         uint32_t b0, uint32_t b1) {
    asm volatile(
        "mma.sync.aligned.m16n8k8.row.col.f32.tf32.tf32.f32 "
        "{%0,%1,%2,%3}, {%4,%5,%6,%7}, {%8,%9}, {%0,%1,%2,%3};"
        : "+f"(c0), "+f"(c1), "+f"(c2), "+f"(c3)
        : "r"(a0), "r"(a1), "r"(a2), "r"(a3), "r"(b0), "r"(b1));
}

// ---------------------------------------------------------------------------
// Launch #1 — slim prep: A convert + noise_sim + mem_update(compute only)
// + clutter insert (20 columns). All identity-copy work now lives in the
// GEMM's tile loads.
//   blocks [0,64)     : A convert
//   blocks [64,192)   : noise similarity
//   blocks [192,448)  : memory update — instant return unless cnt[c]>0
//   block  448        : clutter insert (20 columns)
// ---------------------------------------------------------------------------
__global__ __launch_bounds__(256)
void prep_fused_kernel(const float* __restrict__ features,
                       const int* __restrict__ visible,
                       const int* __restrict__ label,
                       const float* __restrict__ memory,
                       const int* __restrict__ lru,
                       float* __restrict__ out_nsim,
                       float* __restrict__ out_mem,
                       float* __restrict__ out_cb) {
    const int bx = blockIdx.x;

    if (bx < 64) {
        // ================= A conversion =================
        const int base = bx * 4096;
        for (int e = threadIdx.x; e < 4096; e += 256) {
            const int idx = base + e;
            const int m = idx >> 7;
            const int k = idx & 127;
            const int b = m >> 9;
            const int i = m & 511;
            const float x = features[(size_t)(b * FEAT_ROWS + i) * MESH_DIM + k];
            g_A[((size_t)m << 7) | kpos(k)] = to_tf32(x);
        }
        return;
    }

    if (bx < 192) {
        // ================= noise similarity =================
        __shared__ float ns[BATCH * NUM_CLUT][MESH_DIM];
        const int blk = bx - 64;
        const int c = blk >> 1;
        const int j = (blk & 1) * 256 + threadIdx.x;

        for (int idx = threadIdx.x; idx < BATCH * NUM_CLUT * MESH_DIM; idx += 256) {
            const int r = idx >> 7;
            const int v = idx & 127;
            const int bb = r / NUM_CLUT;
            const int kk = r % NUM_CLUT;
            ns[r][v] = features[(size_t)(bb * FEAT_ROWS + MAX_N + kk) * MESH_DIM + v];
        }
        __syncthreads();

        float acc[BATCH * NUM_CLUT];
#pragma unroll
        for (int r = 0; r < BATCH * NUM_CLUT; r++) acc[r] = 0.0f;

        const float* mp = memory + (size_t)c * (MESH_DIM * MAX_N) + j;
#pragma unroll 4
        for (int v = 0; v < MESH_DIM; v++) {
            const float mv = mp[(size_t)v * MAX_N];
#pragma unroll
            for (int r = 0; r < BATCH * NUM_CLUT; r++) acc[r] += ns[r][v] * mv;
        }
#pragma unroll
        for (int r = 0; r < BATCH * NUM_CLUT; r++)
            out_nsim[(size_t)r * CJ + c * MAX_N + j] = acc[r];
        return;
    }

    if (bx < 448) {
        // ================= memory update (compute path only) =================
        const int blk = bx - 192;
        const int c   = blk >> 2;

        int lbl[BATCH];
#pragma unroll
        for (int bb = 0; bb < BATCH; bb++) lbl[bb] = label[bb];
        int cnt = 0;
#pragma unroll
        for (int bb = 0; bb < BATCH; bb++) cnt += (lbl[bb] == c) ? 1 : 0;
        if (cnt == 0) return;   // GEMM writes out_mem = memory for this class

        __shared__ float4 ssqs[8][32];
        const int j0  = (blk & 3) * 128;
        const int t   = threadIdx.x;
        const int jx  = t & 31;
        const int vy  = t >> 5;               // 0..7
        const int j   = j0 + jx * 4;
        const float inv = 1.0f / (float)cnt;

        float w[BATCH][4];
#pragma unroll
        for (int bb = 0; bb < BATCH; bb++)
#pragma unroll
            for (int d = 0; d < 4; d++)
                w[bb][d] = (lbl[bb] == c && visible[bb * MAX_N + j + d] != 0) ? inv : 0.0f;

        const float* mrow = memory + (size_t)c * (MESH_DIM * MAX_N) + j;
        float4 vals[16];
        float4 ssq = make_float4(0.f, 0.f, 0.f, 0.f);
#pragma unroll
        for (int vv = 0; vv < 16; vv++) {
            const int v = vy * 16 + vv;
            float4 m = *reinterpret_cast<const float4*>(mrow + (size_t)v * MAX_N);
            float s[4];
#pragma unroll
            for (int d = 0; d < 4; d++) {
                s[d] = 0.0f;
#pragma unroll
                for (int bb = 0; bb < BATCH; bb++)
                    s[d] += w[bb][d] *
                            features[(size_t)(bb * FEAT_ROWS + j + d) * MESH_DIM + v];
            }
            m.x = 0.9f * m.x + 0.1f * s[0];
            m.y = 0.9f * m.y + 0.1f * s[1];
            m.z = 0.9f * m.z + 0.1f * s[2];
            m.w = 0.9f * m.w + 0.1f * s[3];
            vals[vv] = m;
            ssq.x += m.x * m.x;  ssq.y += m.y * m.y;
            ssq.z += m.z * m.z;  ssq.w += m.w * m.w;
        }
        ssqs[vy][jx] = ssq;
        __syncthreads();

        float4 tot = make_float4(0.f, 0.f, 0.f, 0.f);
#pragma unroll
        for (int y = 0; y < 8; y++) {
            const float4 q = ssqs[y][jx];
            tot.x += q.x; tot.y += q.y; tot.z += q.z; tot.w += q.w;
        }
        float4 rn;
        rn.x = 1.0f / fmaxf(sqrtf(tot.x), 1e-12f);
        rn.y = 1.0f / fmaxf(sqrtf(tot.y), 1e-12f);
        rn.z = 1.0f / fmaxf(sqrtf(tot.z), 1e-12f);
        rn.w = 1.0f / fmaxf(sqrtf(tot.w), 1e-12f);

        float* orow = out_mem + (size_t)c * (MESH_DIM * MAX_N) + j;
#pragma unroll
        for (int vv = 0; vv < 16; vv++) {
            const int v = vy * 16 + vv;
            float4 m = vals[vv];
            m.x *= rn.x; m.y *= rn.y; m.z *= rn.z; m.w *= rn.w;
            *reinterpret_cast<float4*>(orow + (size_t)v * MAX_N) = m;
        }
        return;
    }

    // ================= clutter insert: the 20 new columns =================
    {
        const int t = threadIdx.x;
        if (t >= NB_INS) return;
        const int new_lru = (lru[0] + 1) % (BANK_SIZE / BATCH);
        const int n = new_lru * NB_INS + t;
        const int bb = t / NUM_CLUT;
        const int kk = t % NUM_CLUT;
        const float* nsrc = features + (size_t)(bb * FEAT_ROWS + MAX_N + kk) * MESH_DIM;

        float ssq = 0.0f;
#pragma unroll 8
        for (int v = 0; v < MESH_DIM; v++) {
            const float val = nsrc[v];
            ssq += val * val;
        }
        const float rn = 1.0f / fmaxf(sqrtf(ssq), 1e-12f);

#pragma unroll 8
        for (int v = 0; v < MESH_DIM; v++)
            out_cb[(size_t)v * NCLUT_TOT + n] = nsrc[v] * rn;
    }
}

// ---------------------------------------------------------------------------
// Launch #2 — tf32 mma.sync GEMM (R7 mainloop, regs=64 path) + identity-copy
// emission from the raw smem W tile:
//   memory-region CTAs with cnt[class]==0  -> out_mem tile = raw Ws
//   clutter-region CTAs                    -> out_cb tile = raw Ws, skipping
//                                             the 20-column insert window
// Copy-out uses the SAME per-thread element partition as the tf32 convert
// loop, so no extra __syncthreads is needed between them.
// ---------------------------------------------------------------------------
#define LDK 136
#define TILE_FLOATS (128 * LDK)
#define GEMM_DSMEM (3 * TILE_FLOATS * 4)   // 208,896 bytes

__global__ __launch_bounds__(512)
void sim_gemm_tf32_kernel(const float* __restrict__ memory,
                          const float* __restrict__ clutter,
                          const int* __restrict__ label,
                          const int* __restrict__ lru,
                          float* __restrict__ out,
                          float* __restrict__ out_mem,
                          float* __restrict__ out_cb) {
    extern __shared__ float smem[];
    float* Ws  = smem;                     // [k=128][n=128] (+pad), tf32 after cvt
    float* As0 = smem + TILE_FLOATS;       // [m=128][kpos=128] (+pad)
    float* As1 = As0 + TILE_FLOATS;

    const int tid  = threadIdx.x;
    const int wid  = tid >> 5;
    const int lane = tid & 31;
    const int g    = lane >> 2;            // 0..7
    const int tg   = lane & 3;             // 0..3
    const int wm   = (wid >> 2) * 32;      // 0,32,64,96
    const int wn   = (wid & 3) * 32;       // 0,32,64,96
    const int n0   = blockIdx.x * 128;

    const float* wsrc;
    size_t ldw;
    if (n0 < CJ) {
        wsrc = memory + (size_t)(n0 >> 9) * (MESH_DIM * MAX_N) + (n0 & 511);
        ldw  = MAX_N;
    } else {
        wsrc = clutter + (n0 - CJ);
        ldw  = NCLUT_TOT;
    }

    // ---- initial loads: raw W tile + A tile 0 (cp.async) ----
    {
        const uint32_t wbase = smem_u32(Ws);
        const uint32_t abase = smem_u32(As0);
        for (int c = tid; c < 4096; c += 512) {
            const int row = c >> 5, cid = c & 31;
            CP_ASYNC16(wbase + (uint32_t)(row * LDK + cid * 4) * 4,
                       wsrc + (size_t)row * ldw + cid * 4);
            CP_ASYNC16(abase + (uint32_t)(row * LDK + cid * 4) * 4,
                       g_A + (size_t)row * MESH_DIM + cid * 4);
        }
        CP_COMMIT();
        CP_WAIT0();
    }
    __syncthreads();

    // ---- identity-copy emission from RAW W tile (before tf32 convert) ----
    if (n0 < CJ) {
        const int c = n0 >> 9;
        int cnt = 0;
#pragma unroll
        for (int bb = 0; bb < BATCH; bb++) cnt += (label[bb] == c) ? 1 : 0;
        if (cnt == 0) {
            float* dst = out_mem + (size_t)c * (MESH_DIM * MAX_N) + (n0 & 511);
            for (int e = tid; e < 4096; e += 512) {
                const int k = e >> 5, nc = (e & 31) * 4;
                *reinterpret_cast<float4*>(dst + (size_t)k * MAX_N + nc) =
                    *reinterpret_cast<const float4*>(Ws + k * LDK + nc);
            }
        }
    } else {
        const int nb = n0 - CJ;
        const int new_lru = (lru[0] + 1) % (BANK_SIZE / BATCH);
        const int start = new_lru * NB_INS;
        float* dst = out_cb + nb;
        for (int e = tid; e < 4096; e += 512) {
            const int k = e >> 5, nc = (e & 31) * 4;
            const float4 v = *reinterpret_cast<const float4*>(Ws + k * LDK + nc);
            float* d = dst + (size_t)k * NCLUT_TOT + nc;
            const int ng = nb + nc;
            if (ng + 3 < start || ng >= start + NB_INS) {
                *reinterpret_cast<float4*>(d) = v;       // fully outside window
            } else {                                      // straddle: per-element
                if (ng + 0 < start || ng + 0 >= start + NB_INS) d[0] = v.x;
                if (ng + 1 < start || ng + 1 >= start + NB_INS) d[1] = v.y;
                if (ng + 2 < start || ng + 2 >= start + NB_INS) d[2] = v.z;
                if (ng + 3 < start || ng + 3 >= start + NB_INS) d[3] = v.w;
            }
        }
    }

    // ---- in-smem tf32 conversion of W (same element partition: no sync) ----
    for (int e = tid; e < 4096; e += 512) {
        const int k = e >> 5, nc = (e & 31) * 4;
        float4 v = *reinterpret_cast<float4*>(Ws + k * LDK + nc);
        v.x = to_tf32(v.x); v.y = to_tf32(v.y);
        v.z = to_tf32(v.z); v.w = to_tf32(v.w);
        *reinterpret_cast<float4*>(Ws + k * LDK + nc) = v;
    }
    __syncthreads();

    float* bufs[2] = { As0, As1 };
    const int nidx = wn + g;               // base n for B frags (+ ni*8)

    for (int mt = 0; mt < 16; mt++) {
        const float* cur = bufs[mt & 1];

        if (mt < 15) {
            const float* asrc = g_A + ((size_t)(mt + 1) * 128) * MESH_DIM;
            const uint32_t abase = smem_u32(bufs[(mt + 1) & 1]);
            for (int c = tid; c < 4096; c += 512) {
                const int row = c >> 5, cid = c & 31;
                CP_ASYNC16(abase + (uint32_t)(row * LDK + cid * 4) * 4,
                           asrc + (size_t)row * MESH_DIM + cid * 4);
            }
            CP_COMMIT();
        }

        float acc[2][4][4];
#pragma unroll
        for (int mi = 0; mi < 2; mi++)
#pragma unroll
            for (int ni = 0; ni < 4; ni++)
#pragma unroll
                for (int r = 0; r < 4; r++) acc[mi][ni][r] = 0.0f;

#pragma unroll
        for (int ks = 0; ks < 16; ks++) {
            const int colb = ks * 8 + 2 * tg;     // A: permuted pos (k=ks*8+tg, +4)
            const int colk = ks * 8 + tg;         // B: logical k row

            uint32_t a0[2], a1[2], a2[2], a3[2];
#pragma unroll
            for (int mi = 0; mi < 2; mi++) {
                const float* p = &cur[(wm + mi * 16 + g) * LDK + colb];
                const float2 lo = *reinterpret_cast<const float2*>(p);
                const float2 hi = *reinterpret_cast<const float2*>(p + 8 * LDK);
                a0[mi] = __float_as_uint(lo.x);
                a2[mi] = __float_as_uint(lo.y);
                a1[mi] = __float_as_uint(hi.x);
                a3[mi] = __float_as_uint(hi.y);
            }
            uint32_t b0[4], b1[4];
#pragma unroll
            for (int ni = 0; ni < 4; ni++) {
                b0[ni] = __float_as_uint(Ws[colk * LDK + nidx + ni * 8]);
                b1[ni] = __float_as_uint(Ws[(colk + 4) * LDK + nidx + ni * 8]);
            }
#pragma unroll
            for (int mi = 0; mi < 2; mi++)
#pragma unroll
                for (int ni = 0; ni < 4; ni++)
                    mma_tf32(acc[mi][ni][0], acc[mi][ni][1],
                             acc[mi][ni][2], acc[mi][ni][3],
                             a0[mi], a1[mi], a2[mi], a3[mi],
                             b0[ni], b1[ni]);
        }

        // ---- store D tile ----
#pragma unroll
        for (int mi = 0; mi < 2; mi++) {
            const size_t m = (size_t)(mt * 128 + wm + mi * 16 + g);
#pragma unroll
            for (int ni = 0; ni < 4; ni++) {
                float* o = out + m * NTOT + (n0 + wn + ni * 8 + 2 * tg);
                float2 v0; v0.x = acc[mi][ni][0]; v0.y = acc[mi][ni][1];
                float2 v1; v1.x = acc[mi][ni][2]; v1.y = acc[mi][ni][3];
                *reinterpret_cast<float2*>(o)            = v0;
                *reinterpret_cast<float2*>(o + 8 * NTOT) = v1;
            }
        }

        if (mt < 15) {
            CP_WAIT0();
            __syncthreads();
        }
    }
}

// ---------------------------------------------------------------------------
// Launcher — exactly 2 kernels (ncu -s 5 -c 1 lands on the GEMM).
// ---------------------------------------------------------------------------
extern "C" void kernel_launch(void* const* d_in, const int* in_sizes, int n_in,
                              void* d_out, int out_size) {
    const float* features = (const float*)d_in[0];
    const int*   visible  = (const int*)d_in[1];
    const int*   label    = (const int*)d_in[2];
    const float* memory   = (const float*)d_in[3];
    const float* clutter  = (const float*)d_in[4];
    const int*   lru      = (const int*)d_in[5];

    float* out = (float*)d_out;
    float* out_sim  = out + OUT_SIM_OFF;
    float* out_nsim = out + OUT_NSIM_OFF;
    float* out_mem  = out + OUT_MEM_OFF;
    float* out_cb   = out + OUT_CB_OFF;

    cudaFuncSetAttribute(sim_gemm_tf32_kernel,
                         cudaFuncAttributeMaxDynamicSharedMemorySize, GEMM_DSMEM);

    prep_fused_kernel<<<64 + 128 + 256 + 1, 256>>>(
        features, visible, label, memory, lru,
        out_nsim, out_mem, out_cb);
    sim_gemm_tf32_kernel<<<NTOT / 128, 512, GEMM_DSMEM>>>(memory, clutter,
                                                          label, lru,
                                                          out_sim, out_mem, out_cb);
}

// round 16
// speedup vs baseline: 1.1460x; 1.1460x over previous
#include <cuda_runtime.h>
#include <cuda_bf16.h>
#include <cstdint>

// Problem constants
#define MAX_N     512
#define N_CLASSES 64
#define MESH_DIM  128
#define NUM_CLUT  5
#define BANK_SIZE 4096
#define BATCH     4
#define FEAT_ROWS (MAX_N + NUM_CLUT)          // 517
#define CJ        (N_CLASSES * MAX_N)          // 32768
#define NCLUT_TOT (NUM_CLUT * BANK_SIZE)       // 20480
#define NTOT      (CJ + NCLUT_TOT)             // 53248
#define M_TOT     (BATCH * MAX_N)              // 2048

// Output offsets (element counts)
#define OUT_SIM_OFF   0ULL
#define OUT_SIM_SZ    ((unsigned long long)BATCH * MAX_N * NTOT)
#define OUT_NSIM_OFF  (OUT_SIM_OFF + OUT_SIM_SZ)
#define OUT_NSIM_SZ   ((unsigned long long)BATCH * NUM_CLUT * CJ)
#define OUT_MEM_OFF   (OUT_NSIM_OFF + OUT_NSIM_SZ)
#define OUT_MEM_SZ    ((unsigned long long)N_CLASSES * MESH_DIM * MAX_N)
#define OUT_CB_OFF    (OUT_MEM_OFF + OUT_MEM_SZ)

// ---------------------------------------------------------------------------
// tf32 A scratch (device global — allocation-free rule).
// Row-major [m][k], k permuted within 8-blocks: pos 2t,2t+1 hold k=t,t+4
// so fragment pairs (k, k+4) are one LDS.64.
// ---------------------------------------------------------------------------
__device__ __align__(16) float g_A[(size_t)M_TOT * MESH_DIM];   // 1 MB

__device__ __forceinline__ int kpos(int k) {
    return (k & ~7) | (((k & 3) << 1) | ((k >> 2) & 1));
}

__device__ __forceinline__ float to_tf32(float x) {
    uint32_t u;
    asm("cvt.rna.tf32.f32 %0, %1;" : "=r"(u) : "f"(x));
    return __uint_as_float(u);
}

__device__ __forceinline__ uint32_t smem_u32(const void* p) {
    uint32_t a;
    asm("{ .reg .u64 t; cvta.to.shared.u64 t, %1; cvt.u32.u64 %0, t; }" : "=r"(a) : "l"(p));
    return a;
}

#define CP_ASYNC16(saddr, gptr) \
    asm volatile("cp.async.cg.shared.global [%0], [%1], 16;" :: "r"(saddr), "l"(gptr))
#define CP_COMMIT() asm volatile("cp.async.commit_group;")
#define CP_WAIT0()  asm volatile("cp.async.wait_group 0;")

// m16n8k8 tf32 MMA (sm_80 baseline — works at compute_103)
__device__ __forceinline__ void mma_tf32(float& c0, float& c1, float& c2, float& c3,
                                         uint32_t a0, uint32_t a1, uint32_t a2, uint32_t a3,
                                         uint32_t b0, uint32_t b1) {
    asm volatile(
        "mma.sync.aligned.m16n8k8.row.col.f32.tf32.tf32.f32 "
        "{%0,%1,%2,%3}, {%4,%5,%6,%7}, {%8,%9}, {%0,%1,%2,%3};"
        : "+f"(c0), "+f"(c1), "+f"(c2), "+f"(c3)
        : "r"(a0), "r"(a1), "r"(a2), "r"(a3), "r"(b0), "r"(b1));
}

// ---------------------------------------------------------------------------
// Kernel A — A tf32 convert (serial prefix; GEMM's only dependency)
// ---------------------------------------------------------------------------
__global__ __launch_bounds__(256)
void a_convert_kernel(const float* __restrict__ features) {
    const int base = blockIdx.x * 1024;
    for (int e = threadIdx.x; e < 1024; e += 256) {
        const int idx = base + e;
        const int m = idx >> 7;
        const int k = idx & 127;
        const int b = m >> 9;
        const int i = m & 511;
        const float x = features[(size_t)(b * FEAT_ROWS + i) * MESH_DIM + k];
        g_A[((size_t)m << 7) | kpos(k)] = to_tf32(x);
    }
}

// ---------------------------------------------------------------------------
// Kernel B — aux (runs CONCURRENTLY with the GEMM on a forked stream):
//   blocks [0,128)    : noise similarity
//   blocks [128,384)  : memory update
//   blocks [384,464)  : clutter bank
// Small footprint (256 thr, <=10.2KB smem) -> co-resides with GEMM CTAs.
// ---------------------------------------------------------------------------
__global__ __launch_bounds__(256)
void aux_kernel(const float* __restrict__ features,
                const int* __restrict__ visible,
                const int* __restrict__ label,
                const float* __restrict__ memory,
                const float* __restrict__ clutter,
                const int* __restrict__ lru,
                float* __restrict__ out_nsim,
                float* __restrict__ out_mem,
                float* __restrict__ out_cb) {
    const int bx = blockIdx.x;

    if (bx < 128) {
        // ================= noise similarity =================
        __shared__ float ns[BATCH * NUM_CLUT][MESH_DIM];
        const int c = bx >> 1;
        const int j = (bx & 1) * 256 + threadIdx.x;

        for (int idx = threadIdx.x; idx < BATCH * NUM_CLUT * MESH_DIM; idx += 256) {
            const int r = idx >> 7;
            const int v = idx & 127;
            const int bb = r / NUM_CLUT;
            const int kk = r % NUM_CLUT;
            ns[r][v] = features[(size_t)(bb * FEAT_ROWS + MAX_N + kk) * MESH_DIM + v];
        }
        __syncthreads();

        float acc[BATCH * NUM_CLUT];
#pragma unroll
        for (int r = 0; r < BATCH * NUM_CLUT; r++) acc[r] = 0.0f;

        const float* mp = memory + (size_t)c * (MESH_DIM * MAX_N) + j;
#pragma unroll 4
        for (int v = 0; v < MESH_DIM; v++) {
            const float mv = mp[(size_t)v * MAX_N];
#pragma unroll
            for (int r = 0; r < BATCH * NUM_CLUT; r++) acc[r] += ns[r][v] * mv;
        }
#pragma unroll
        for (int r = 0; r < BATCH * NUM_CLUT; r++)
            out_nsim[(size_t)r * CJ + c * MAX_N + j] = acc[r];
        return;
    }

    if (bx < 384) {
        // ================= memory update (float4 over j) =================
        __shared__ float4 ssqs[8][32];
        const int blk = bx - 128;
        const int c   = blk >> 2;
        const int j0  = (blk & 3) * 128;
        const int t   = threadIdx.x;
        const int jx  = t & 31;
        const int vy  = t >> 5;               // 0..7
        const int j   = j0 + jx * 4;

        int lbl[BATCH];
#pragma unroll
        for (int bb = 0; bb < BATCH; bb++) lbl[bb] = label[bb];
        int cnt = 0;
#pragma unroll
        for (int bb = 0; bb < BATCH; bb++) cnt += (lbl[bb] == c) ? 1 : 0;
        const float inv = (cnt > 0) ? (1.0f / (float)cnt) : 0.0f;

        float w[BATCH][4];
#pragma unroll
        for (int bb = 0; bb < BATCH; bb++)
#pragma unroll
            for (int d = 0; d < 4; d++)
                w[bb][d] = (lbl[bb] == c && visible[bb * MAX_N + j + d] != 0) ? inv : 0.0f;

        const float* mrow = memory + (size_t)c * (MESH_DIM * MAX_N) + j;
        float4 vals[16];
        float4 ssq = make_float4(0.f, 0.f, 0.f, 0.f);
#pragma unroll
        for (int vv = 0; vv < 16; vv++) {
            const int v = vy * 16 + vv;
            float4 m = *reinterpret_cast<const float4*>(mrow + (size_t)v * MAX_N);
            if (cnt > 0) {
                float s[4];
#pragma unroll
                for (int d = 0; d < 4; d++) {
                    s[d] = 0.0f;
#pragma unroll
                    for (int bb = 0; bb < BATCH; bb++)
                        s[d] += w[bb][d] *
                                features[(size_t)(bb * FEAT_ROWS + j + d) * MESH_DIM + v];
                }
                m.x = 0.9f * m.x + 0.1f * s[0];
                m.y = 0.9f * m.y + 0.1f * s[1];
                m.z = 0.9f * m.z + 0.1f * s[2];
                m.w = 0.9f * m.w + 0.1f * s[3];
            }
            vals[vv] = m;
            ssq.x += m.x * m.x;  ssq.y += m.y * m.y;
            ssq.z += m.z * m.z;  ssq.w += m.w * m.w;
        }
        ssqs[vy][jx] = ssq;
        __syncthreads();

        float4 tot = make_float4(0.f, 0.f, 0.f, 0.f);
#pragma unroll
        for (int y = 0; y < 8; y++) {
            const float4 q = ssqs[y][jx];
            tot.x += q.x; tot.y += q.y; tot.z += q.z; tot.w += q.w;
        }
        float4 rn;
        rn.x = 1.0f / fmaxf(sqrtf(tot.x), 1e-12f);
        rn.y = 1.0f / fmaxf(sqrtf(tot.y), 1e-12f);
        rn.z = 1.0f / fmaxf(sqrtf(tot.z), 1e-12f);
        rn.w = 1.0f / fmaxf(sqrtf(tot.w), 1e-12f);

        float* orow = out_mem + (size_t)c * (MESH_DIM * MAX_N) + j;
#pragma unroll
        for (int vv = 0; vv < 16; vv++) {
            const int v = vy * 16 + vv;
            float4 m = vals[vv];
            m.x *= rn.x; m.y *= rn.y; m.z *= rn.z; m.w *= rn.w;
            *reinterpret_cast<float4*>(orow + (size_t)v * MAX_N) = m;
        }
        return;
    }

    // ================= clutter bank update =================
    {
        const int n = (bx - 384) * 256 + threadIdx.x;   // 0..20479
        const int new_lru = (lru[0] + 1) % (BANK_SIZE / BATCH);
        const int start = new_lru * (NUM_CLUT * BATCH);

        const bool upd = (n >= start) && (n < start + NUM_CLUT * BATCH);
        const int mm = n - start;
        const int bb = upd ? (mm / NUM_CLUT) : 0;
        const int kk = upd ? (mm % NUM_CLUT) : 0;
        const float* nsrc = features + (size_t)(bb * FEAT_ROWS + MAX_N + kk) * MESH_DIM;

        float ssq = 0.0f;
#pragma unroll 8
        for (int v = 0; v < MESH_DIM; v++) {
            const float val = upd ? nsrc[v] : clutter[(size_t)v * NCLUT_TOT + n];
            ssq += val * val;
        }
        const float rn = 1.0f / fmaxf(sqrtf(ssq), 1e-12f);

#pragma unroll 8
        for (int v = 0; v < MESH_DIM; v++) {
            const float val = upd ? nsrc[v] : clutter[(size_t)v * NCLUT_TOT + n];
            out_cb[(size_t)v * NCLUT_TOT + n] = val * rn;
        }
    }
}

// ---------------------------------------------------------------------------
// Kernel C — tf32 mma.sync GEMM (R7-EXACT champion: 227.8us, regs=64).
//   out[m][n] = A[m][:128] . W[:][n]
// ---------------------------------------------------------------------------
#define LDK 136
#define TILE_FLOATS (128 * LDK)
#define GEMM_DSMEM (3 * TILE_FLOATS * 4)   // 208,896 bytes

__global__ __launch_bounds__(512)
void sim_gemm_tf32_kernel(const float* __restrict__ memory,
                          const float* __restrict__ clutter,
                          float* __restrict__ out) {
    extern __shared__ float smem[];
    float* Ws  = smem;                     // [k=128][n=128] (+pad), tf32 after cvt
    float* As0 = smem + TILE_FLOATS;       // [m=128][kpos=128] (+pad)
    float* As1 = As0 + TILE_FLOATS;

    const int tid  = threadIdx.x;
    const int wid  = tid >> 5;
    const int lane = tid & 31;
    const int g    = lane >> 2;            // 0..7
    const int tg   = lane & 3;             // 0..3
    const int wm   = (wid >> 2) * 32;      // 0,32,64,96
    const int wn   = (wid & 3) * 32;       // 0,32,64,96
    const int n0   = blockIdx.x * 128;

    const float* wsrc;
    size_t ldw;
    if (n0 < CJ) {
        wsrc = memory + (size_t)(n0 >> 9) * (MESH_DIM * MAX_N) + (n0 & 511);
        ldw  = MAX_N;
    } else {
        wsrc = clutter + (n0 - CJ);
        ldw  = NCLUT_TOT;
    }

    // ---- initial loads: raw W tile + A tile 0 (cp.async) ----
    {
        const uint32_t wbase = smem_u32(Ws);
        const uint32_t abase = smem_u32(As0);
        for (int c = tid; c < 4096; c += 512) {
            const int row = c >> 5, cid = c & 31;
            CP_ASYNC16(wbase + (uint32_t)(row * LDK + cid * 4) * 4,
                       wsrc + (size_t)row * ldw + cid * 4);
            CP_ASYNC16(abase + (uint32_t)(row * LDK + cid * 4) * 4,
                       g_A + (size_t)row * MESH_DIM + cid * 4);
        }
        CP_COMMIT();
        CP_WAIT0();
    }
    __syncthreads();

    // ---- in-smem tf32 conversion of W (once per CTA) ----
    for (int e = tid; e < 4096; e += 512) {
        const int k = e >> 5, nc = (e & 31) * 4;
        float4 v = *reinterpret_cast<float4*>(Ws + k * LDK + nc);
        v.x = to_tf32(v.x); v.y = to_tf32(v.y);
        v.z = to_tf32(v.z); v.w = to_tf32(v.w);
        *reinterpret_cast<float4*>(Ws + k * LDK + nc) = v;
    }
    __syncthreads();

    float* bufs[2] = { As0, As1 };
    const int nidx = wn + g;               // base n for B frags (+ ni*8)

    for (int mt = 0; mt < 16; mt++) {
        const float* cur = bufs[mt & 1];

        if (mt < 15) {
            const float* asrc = g_A + ((size_t)(mt + 1) * 128) * MESH_DIM;
            const uint32_t abase = smem_u32(bufs[(mt + 1) & 1]);
            for (int c = tid; c < 4096; c += 512) {
                const int row = c >> 5, cid = c & 31;
                CP_ASYNC16(abase + (uint32_t)(row * LDK + cid * 4) * 4,
                           asrc + (size_t)row * MESH_DIM + cid * 4);
            }
            CP_COMMIT();
        }

        float acc[2][4][4];
#pragma unroll
        for (int mi = 0; mi < 2; mi++)
#pragma unroll
            for (int ni = 0; ni < 4; ni++)
#pragma unroll
                for (int r = 0; r < 4; r++) acc[mi][ni][r] = 0.0f;

#pragma unroll
        for (int ks = 0; ks < 16; ks++) {
            const int colb = ks * 8 + 2 * tg;     // A: permuted pos (k=ks*8+tg, +4)
            const int colk = ks * 8 + tg;         // B: logical k row

            uint32_t a0[2], a1[2], a2[2], a3[2];
#pragma unroll
            for (int mi = 0; mi < 2; mi++) {
                const float* p = &cur[(wm + mi * 16 + g) * LDK + colb];
                const float2 lo = *reinterpret_cast<const float2*>(p);
                const float2 hi = *reinterpret_cast<const float2*>(p + 8 * LDK);
                a0[mi] = __float_as_uint(lo.x);
                a2[mi] = __float_as_uint(lo.y);
                a1[mi] = __float_as_uint(hi.x);
                a3[mi] = __float_as_uint(hi.y);
            }
            uint32_t b0[4], b1[4];
#pragma unroll
            for (int ni = 0; ni < 4; ni++) {
                b0[ni] = __float_as_uint(Ws[colk * LDK + nidx + ni * 8]);
                b1[ni] = __float_as_uint(Ws[(colk + 4) * LDK + nidx + ni * 8]);
            }
#pragma unroll
            for (int mi = 0; mi < 2; mi++)
#pragma unroll
                for (int ni = 0; ni < 4; ni++)
                    mma_tf32(acc[mi][ni][0], acc[mi][ni][1],
                             acc[mi][ni][2], acc[mi][ni][3],
                             a0[mi], a1[mi], a2[mi], a3[mi],
                             b0[ni], b1[ni]);
        }

        // ---- store D tile ----
#pragma unroll
        for (int mi = 0; mi < 2; mi++) {
            const size_t m = (size_t)(mt * 128 + wm + mi * 16 + g);
#pragma unroll
            for (int ni = 0; ni < 4; ni++) {
                float* o = out + m * NTOT + (n0 + wn + ni * 8 + 2 * tg);
                float2 v0; v0.x = acc[mi][ni][0]; v0.y = acc[mi][ni][1];
                float2 v1; v1.x = acc[mi][ni][2]; v1.y = acc[mi][ni][3];
                *reinterpret_cast<float2*>(o)            = v0;
                *reinterpret_cast<float2*>(o + 8 * NTOT) = v1;
            }
        }

        if (mt < 15) {
            CP_WAIT0();
            __syncthreads();
        }
    }
}

// ---------------------------------------------------------------------------
// Launcher — fork-join graph: a_convert -> { GEMM (main) || aux (side) } -> join.
// Streams/events are host-side objects created lazily on the (uncaptured)
// correctness call; no device memory is allocated.
// ---------------------------------------------------------------------------
extern "C" void kernel_launch(void* const* d_in, const int* in_sizes, int n_in,
                              void* d_out, int out_size) {
    const float* features = (const float*)d_in[0];
    const int*   visible  = (const int*)d_in[1];
    const int*   label    = (const int*)d_in[2];
    const float* memory   = (const float*)d_in[3];
    const float* clutter  = (const float*)d_in[4];
    const int*   lru      = (const int*)d_in[5];

    float* out = (float*)d_out;
    float* out_sim  = out + OUT_SIM_OFF;
    float* out_nsim = out + OUT_NSIM_OFF;
    float* out_mem  = out + OUT_MEM_OFF;
    float* out_cb   = out + OUT_CB_OFF;

    static cudaStream_t s_aux = nullptr;
    static cudaEvent_t  ev_fork = nullptr, ev_join = nullptr;
    if (s_aux == nullptr) {
        cudaStreamCreateWithFlags(&s_aux, cudaStreamNonBlocking);
        cudaEventCreateWithFlags(&ev_fork, cudaEventDisableTiming);
        cudaEventCreateWithFlags(&ev_join, cudaEventDisableTiming);
        cudaFuncSetAttribute(sim_gemm_tf32_kernel,
                             cudaFuncAttributeMaxDynamicSharedMemorySize, GEMM_DSMEM);
    }

    // Serial prefix: A conversion (GEMM's only dependency).
    a_convert_kernel<<<M_TOT * MESH_DIM / 1024, 256>>>(features);

    // Fork: aux on side stream, GEMM on main stream — run concurrently.
    cudaEventRecord(ev_fork, 0);
    cudaStreamWaitEvent(s_aux, ev_fork, 0);
    aux_kernel<<<128 + 256 + NCLUT_TOT / 256, 256, 0, s_aux>>>(
        features, visible, label, memory, clutter, lru,
        out_nsim, out_mem, out_cb);
    cudaEventRecord(ev_join, s_aux);

    sim_gemm_tf32_kernel<<<NTOT / 128, 512, GEMM_DSMEM>>>(memory, clutter, out_sim);

    // Join: main stream waits for aux before the launch returns to the graph.
    cudaStreamWaitEvent(0, ev_join, 0);
}

// round 17
// speedup vs baseline: 1.1463x; 1.0003x over previous
#include <cuda_runtime.h>
#include <cuda_bf16.h>
#include <cstdint>

// Problem constants
#define MAX_N     512
#define N_CLASSES 64
#define MESH_DIM  128
#define NUM_CLUT  5
#define BANK_SIZE 4096
#define BATCH     4
#define FEAT_ROWS (MAX_N + NUM_CLUT)          // 517
#define CJ        (N_CLASSES * MAX_N)          // 32768
#define NCLUT_TOT (NUM_CLUT * BANK_SIZE)       // 20480
#define NTOT      (CJ + NCLUT_TOT)             // 53248
#define M_TOT     (BATCH * MAX_N)              // 2048
#define NB_INS    (NUM_CLUT * BATCH)           // 20 inserted columns

// Output offsets (element counts)
#define OUT_SIM_OFF   0ULL
#define OUT_SIM_SZ    ((unsigned long long)BATCH * MAX_N * NTOT)
#define OUT_NSIM_OFF  (OUT_SIM_OFF + OUT_SIM_SZ)
#define OUT_NSIM_SZ   ((unsigned long long)BATCH * NUM_CLUT * CJ)
#define OUT_MEM_OFF   (OUT_NSIM_OFF + OUT_NSIM_SZ)
#define OUT_MEM_SZ    ((unsigned long long)N_CLASSES * MESH_DIM * MAX_N)
#define OUT_CB_OFF    (OUT_MEM_OFF + OUT_MEM_SZ)

// ---------------------------------------------------------------------------
// tf32 A scratch (device global — allocation-free rule).
// Row-major [m][k], k permuted within 8-blocks: pos 2t,2t+1 hold k=t,t+4
// so fragment pairs (k, k+4) are one LDS.64.
// ---------------------------------------------------------------------------
__device__ __align__(16) float g_A[(size_t)M_TOT * MESH_DIM];   // 1 MB

__device__ __forceinline__ float to_tf32(float x) {
    uint32_t u;
    asm("cvt.rna.tf32.f32 %0, %1;" : "=r"(u) : "f"(x));
    return __uint_as_float(u);
}

__device__ __forceinline__ uint32_t smem_u32(const void* p) {
    uint32_t a;
    asm("{ .reg .u64 t; cvta.to.shared.u64 t, %1; cvt.u32.u64 %0, t; }" : "=r"(a) : "l"(p));
    return a;
}

#define CP_ASYNC16(saddr, gptr) \
    asm volatile("cp.async.cg.shared.global [%0], [%1], 16;" :: "r"(saddr), "l"(gptr))
#define CP_COMMIT() asm volatile("cp.async.commit_group;")
#define CP_WAIT0()  asm volatile("cp.async.wait_group 0;")

// m16n8k8 tf32 MMA (sm_80 baseline — works at compute_103)
__device__ __forceinline__ void mma_tf32(float& c0, float& c1, float& c2, float& c3,
                                         uint32_t a0, uint32_t a1, uint32_t a2, uint32_t a3,
                                         uint32_t b0, uint32_t b1) {
    asm volatile(
        "mma.sync.aligned.m16n8k8.row.col.f32.tf32.tf32.f32 "
        "{%0,%1,%2,%3}, {%4,%5,%6,%7}, {%8,%9}, {%0,%1,%2,%3};"
        : "+f"(c0), "+f"(c1), "+f"(c2), "+f"(c3)
        : "r"(a0), "r"(a1), "r"(a2), "r"(a3), "r"(b0), "r"(b1));
}

// ---------------------------------------------------------------------------
// Kernel A — A tf32 convert, vectorized (float4 x2 per thread).
// Each thread handles one 8-wide k-group: permuted order {k0,k4,k1,k5,k2,k6,k3,k7}.
// 32768 groups over 128 blocks x 256 threads.
// ---------------------------------------------------------------------------
__global__ __launch_bounds__(256)
void a_convert_kernel(const float* __restrict__ features) {
    const int gidx = blockIdx.x * 256 + threadIdx.x;    // 0..32767
    const int m  = gidx >> 4;
    const int gk = (gidx & 15) * 8;
    const int b  = m >> 9;
    const int i  = m & 511;
    const float* src = features + (size_t)(b * FEAT_ROWS + i) * MESH_DIM + gk;
    const float4 x0 = *reinterpret_cast<const float4*>(src);
    const float4 x1 = *reinterpret_cast<const float4*>(src + 4);
    float4 y0, y1;
    y0.x = to_tf32(x0.x); y0.y = to_tf32(x1.x);
    y0.z = to_tf32(x0.y); y0.w = to_tf32(x1.y);
    y1.x = to_tf32(x0.z); y1.y = to_tf32(x1.z);
    y1.z = to_tf32(x0.w); y1.w = to_tf32(x1.w);
    float* dst = g_A + ((size_t)m << 7) + gk;
    *reinterpret_cast<float4*>(dst)     = y0;
    *reinterpret_cast<float4*>(dst + 4) = y1;
}

// ---------------------------------------------------------------------------
// Kernel B — aux (concurrent with a_convert + GEMM on a forked stream),
// with algebraic fast paths (inputs are pre-L2-normalized):
//   blocks [0,128)    : noise similarity
//   blocks [128,384)  : memory update  (cnt==0 -> pure copy)
//   blocks [384,464)  : clutter bank   (non-inserted columns -> pure copy)
// ---------------------------------------------------------------------------
__global__ __launch_bounds__(256)
void aux_kernel(const float* __restrict__ features,
                const int* __restrict__ visible,
                const int* __restrict__ label,
                const float* __restrict__ memory,
                const float* __restrict__ clutter,
                const int* __restrict__ lru,
                float* __restrict__ out_nsim,
                float* __restrict__ out_mem,
                float* __restrict__ out_cb) {
    const int bx = blockIdx.x;

    if (bx < 128) {
        // ================= noise similarity =================
        __shared__ float ns[BATCH * NUM_CLUT][MESH_DIM];
        const int c = bx >> 1;
        const int j = (bx & 1) * 256 + threadIdx.x;

        for (int idx = threadIdx.x; idx < BATCH * NUM_CLUT * MESH_DIM; idx += 256) {
            const int r = idx >> 7;
            const int v = idx & 127;
            const int bb = r / NUM_CLUT;
            const int kk = r % NUM_CLUT;
            ns[r][v] = features[(size_t)(bb * FEAT_ROWS + MAX_N + kk) * MESH_DIM + v];
        }
        __syncthreads();

        float acc[BATCH * NUM_CLUT];
#pragma unroll
        for (int r = 0; r < BATCH * NUM_CLUT; r++) acc[r] = 0.0f;

        const float* mp = memory + (size_t)c * (MESH_DIM * MAX_N) + j;
#pragma unroll 4
        for (int v = 0; v < MESH_DIM; v++) {
            const float mv = mp[(size_t)v * MAX_N];
#pragma unroll
            for (int r = 0; r < BATCH * NUM_CLUT; r++) acc[r] += ns[r][v] * mv;
        }
#pragma unroll
        for (int r = 0; r < BATCH * NUM_CLUT; r++)
            out_nsim[(size_t)r * CJ + c * MAX_N + j] = acc[r];
        return;
    }

    if (bx < 384) {
        // ================= memory update =================
        const int blk = bx - 128;
        const int c   = blk >> 2;
        const int j0  = (blk & 3) * 128;
        const int t   = threadIdx.x;

        int lbl[BATCH];
#pragma unroll
        for (int bb = 0; bb < BATCH; bb++) lbl[bb] = label[bb];
        int cnt = 0;
#pragma unroll
        for (int bb = 0; bb < BATCH; bb++) cnt += (lbl[bb] == c) ? 1 : 0;

        const float* msrc = memory  + (size_t)c * (MESH_DIM * MAX_N) + j0;
        float*       mdst = out_mem + (size_t)c * (MESH_DIM * MAX_N) + j0;

        if (cnt == 0) {
            // rows are unit-norm: l2n(0.9m+0.1m) = m. Pure copy.
            for (int e = t; e < 4096; e += 256) {
                const int v  = e >> 5;
                const int jq = (e & 31) * 4;
                *reinterpret_cast<float4*>(mdst + (size_t)v * MAX_N + jq) =
                    *reinterpret_cast<const float4*>(msrc + (size_t)v * MAX_N + jq);
            }
            return;
        }

        __shared__ float4 ssqs[8][32];
        const int jx  = t & 31;
        const int vy  = t >> 5;               // 0..7
        const int j   = j0 + jx * 4;
        const float inv = 1.0f / (float)cnt;

        float w[BATCH][4];
#pragma unroll
        for (int bb = 0; bb < BATCH; bb++)
#pragma unroll
            for (int d = 0; d < 4; d++)
                w[bb][d] = (lbl[bb] == c && visible[bb * MAX_N + j + d] != 0) ? inv : 0.0f;

        const float* mrow = memory + (size_t)c * (MESH_DIM * MAX_N) + j;
        float4 vals[16];
        float4 ssq = make_float4(0.f, 0.f, 0.f, 0.f);
#pragma unroll
        for (int vv = 0; vv < 16; vv++) {
            const int v = vy * 16 + vv;
            float4 m = *reinterpret_cast<const float4*>(mrow + (size_t)v * MAX_N);
            float s[4];
#pragma unroll
            for (int d = 0; d < 4; d++) {
                s[d] = 0.0f;
#pragma unroll
                for (int bb = 0; bb < BATCH; bb++)
                    s[d] += w[bb][d] *
                            features[(size_t)(bb * FEAT_ROWS + j + d) * MESH_DIM + v];
            }
            m.x = 0.9f * m.x + 0.1f * s[0];
            m.y = 0.9f * m.y + 0.1f * s[1];
            m.z = 0.9f * m.z + 0.1f * s[2];
            m.w = 0.9f * m.w + 0.1f * s[3];
            vals[vv] = m;
            ssq.x += m.x * m.x;  ssq.y += m.y * m.y;
            ssq.z += m.z * m.z;  ssq.w += m.w * m.w;
        }
        ssqs[vy][jx] = ssq;
        __syncthreads();

        float4 tot = make_float4(0.f, 0.f, 0.f, 0.f);
#pragma unroll
        for (int y = 0; y < 8; y++) {
            const float4 q = ssqs[y][jx];
            tot.x += q.x; tot.y += q.y; tot.z += q.z; tot.w += q.w;
        }
        float4 rn;
        rn.x = 1.0f / fmaxf(sqrtf(tot.x), 1e-12f);
        rn.y = 1.0f / fmaxf(sqrtf(tot.y), 1e-12f);
        rn.z = 1.0f / fmaxf(sqrtf(tot.z), 1e-12f);
        rn.w = 1.0f / fmaxf(sqrtf(tot.w), 1e-12f);

        float* orow = out_mem + (size_t)c * (MESH_DIM * MAX_N) + j;
#pragma unroll
        for (int vv = 0; vv < 16; vv++) {
            const int v = vy * 16 + vv;
            float4 m = vals[vv];
            m.x *= rn.x; m.y *= rn.y; m.z *= rn.z; m.w *= rn.w;
            *reinterpret_cast<float4*>(orow + (size_t)v * MAX_N) = m;
        }
        return;
    }

    // ================= clutter bank update =================
    {
        const int n = (bx - 384) * 256 + threadIdx.x;   // 0..20479
        const int new_lru = (lru[0] + 1) % (BANK_SIZE / BATCH);
        const int start = new_lru * NB_INS;

        const bool upd = (n >= start) && (n < start + NB_INS);

        if (!upd) {
            // column already unit-norm: l2n(col) = col. One-pass copy.
#pragma unroll 8
            for (int v = 0; v < MESH_DIM; v++)
                out_cb[(size_t)v * NCLUT_TOT + n] = clutter[(size_t)v * NCLUT_TOT + n];
            return;
        }

        const int mm = n - start;
        const int bb = mm / NUM_CLUT;
        const int kk = mm % NUM_CLUT;
        const float* nsrc = features + (size_t)(bb * FEAT_ROWS + MAX_N + kk) * MESH_DIM;

        float ssq = 0.0f;
#pragma unroll 8
        for (int v = 0; v < MESH_DIM; v++) {
            const float val = nsrc[v];
            ssq += val * val;
        }
        const float rn = 1.0f / fmaxf(sqrtf(ssq), 1e-12f);

#pragma unroll 8
        for (int v = 0; v < MESH_DIM; v++)
            out_cb[(size_t)v * NCLUT_TOT + n] = nsrc[v] * rn;
    }
}

// ---------------------------------------------------------------------------
// Kernel C — tf32 mma.sync GEMM (R7-EXACT champion: 227.8us, regs=64).
//   out[m][n] = A[m][:128] . W[:][n]
// ---------------------------------------------------------------------------
#define LDK 136
#define TILE_FLOATS (128 * LDK)
#define GEMM_DSMEM (3 * TILE_FLOATS * 4)   // 208,896 bytes

__global__ __launch_bounds__(512)
void sim_gemm_tf32_kernel(const float* __restrict__ memory,
                          const float* __restrict__ clutter,
                          float* __restrict__ out) {
    extern __shared__ float smem[];
    float* Ws  = smem;                     // [k=128][n=128] (+pad), tf32 after cvt
    float* As0 = smem + TILE_FLOATS;       // [m=128][kpos=128] (+pad)
    float* As1 = As0 + TILE_FLOATS;

    const int tid  = threadIdx.x;
    const int wid  = tid >> 5;
    const int lane = tid & 31;
    const int g    = lane >> 2;            // 0..7
    const int tg   = lane & 3;             // 0..3
    const int wm   = (wid >> 2) * 32;      // 0,32,64,96
    const int wn   = (wid & 3) * 32;       // 0,32,64,96
    const int n0   = blockIdx.x * 128;

    const float* wsrc;
    size_t ldw;
    if (n0 < CJ) {
        wsrc = memory + (size_t)(n0 >> 9) * (MESH_DIM * MAX_N) + (n0 & 511);
        ldw  = MAX_N;
    } else {
        wsrc = clutter + (n0 - CJ);
        ldw  = NCLUT_TOT;
    }

    // ---- initial loads: raw W tile + A tile 0 (cp.async) ----
    {
        const uint32_t wbase = smem_u32(Ws);
        const uint32_t abase = smem_u32(As0);
        for (int c = tid; c < 4096; c += 512) {
            const int row = c >> 5, cid = c & 31;
            CP_ASYNC16(wbase + (uint32_t)(row * LDK + cid * 4) * 4,
                       wsrc + (size_t)row * ldw + cid * 4);
            CP_ASYNC16(abase + (uint32_t)(row * LDK + cid * 4) * 4,
                       g_A + (size_t)row * MESH_DIM + cid * 4);
        }
        CP_COMMIT();
        CP_WAIT0();
    }
    __syncthreads();

    // ---- in-smem tf32 conversion of W (once per CTA) ----
    for (int e = tid; e < 4096; e += 512) {
        const int k = e >> 5, nc = (e & 31) * 4;
        float4 v = *reinterpret_cast<float4*>(Ws + k * LDK + nc);
        v.x = to_tf32(v.x); v.y = to_tf32(v.y);
        v.z = to_tf32(v.z); v.w = to_tf32(v.w);
        *reinterpret_cast<float4*>(Ws + k * LDK + nc) = v;
    }
    __syncthreads();

    float* bufs[2] = { As0, As1 };
    const int nidx = wn + g;               // base n for B frags (+ ni*8)

    for (int mt = 0; mt < 16; mt++) {
        const float* cur = bufs[mt & 1];

        if (mt < 15) {
            const float* asrc = g_A + ((size_t)(mt + 1) * 128) * MESH_DIM;
            const uint32_t abase = smem_u32(bufs[(mt + 1) & 1]);
            for (int c = tid; c < 4096; c += 512) {
                const int row = c >> 5, cid = c & 31;
                CP_ASYNC16(abase + (uint32_t)(row * LDK + cid * 4) * 4,
                           asrc + (size_t)row * MESH_DIM + cid * 4);
            }
            CP_COMMIT();
        }

        float acc[2][4][4];
#pragma unroll
        for (int mi = 0; mi < 2; mi++)
#pragma unroll
            for (int ni = 0; ni < 4; ni++)
#pragma unroll
                for (int r = 0; r < 4; r++) acc[mi][ni][r] = 0.0f;

#pragma unroll
        for (int ks = 0; ks < 16; ks++) {
            const int colb = ks * 8 + 2 * tg;     // A: permuted pos (k=ks*8+tg, +4)
            const int colk = ks * 8 + tg;         // B: logical k row

            uint32_t a0[2], a1[2], a2[2], a3[2];
#pragma unroll
            for (int mi = 0; mi < 2; mi++) {
                const float* p = &cur[(wm + mi * 16 + g) * LDK + colb];
                const float2 lo = *reinterpret_cast<const float2*>(p);
                const float2 hi = *reinterpret_cast<const float2*>(p + 8 * LDK);
                a0[mi] = __float_as_uint(lo.x);
                a2[mi] = __float_as_uint(lo.y);
                a1[mi] = __float_as_uint(hi.x);
                a3[mi] = __float_as_uint(hi.y);
            }
            uint32_t b0[4], b1[4];
#pragma unroll
            for (int ni = 0; ni < 4; ni++) {
                b0[ni] = __float_as_uint(Ws[colk * LDK + nidx + ni * 8]);
                b1[ni] = __float_as_uint(Ws[(colk + 4) * LDK + nidx + ni * 8]);
            }
#pragma unroll
            for (int mi = 0; mi < 2; mi++)
#pragma unroll
                for (int ni = 0; ni < 4; ni++)
                    mma_tf32(acc[mi][ni][0], acc[mi][ni][1],
                             acc[mi][ni][2], acc[mi][ni][3],
                             a0[mi], a1[mi], a2[mi], a3[mi],
                             b0[ni], b1[ni]);
        }

        // ---- store D tile ----
#pragma unroll
        for (int mi = 0; mi < 2; mi++) {
            const size_t m = (size_t)(mt * 128 + wm + mi * 16 + g);
#pragma unroll
            for (int ni = 0; ni < 4; ni++) {
                float* o = out + m * NTOT + (n0 + wn + ni * 8 + 2 * tg);
                float2 v0; v0.x = acc[mi][ni][0]; v0.y = acc[mi][ni][1];
                float2 v1; v1.x = acc[mi][ni][2]; v1.y = acc[mi][ni][3];
                *reinterpret_cast<float2*>(o)            = v0;
                *reinterpret_cast<float2*>(o + 8 * NTOT) = v1;
            }
        }

        if (mt < 15) {
            CP_WAIT0();
            __syncthreads();
        }
    }
}

// ---------------------------------------------------------------------------
// Launcher — fork-join graph:
//   fork at t=0: aux (side stream) runs concurrent with a_convert + GEMM.
//   main stream: a_convert -> GEMM; join waits for aux.
// Streams/events created lazily on the uncaptured correctness call.
// ---------------------------------------------------------------------------
extern "C" void kernel_launch(void* const* d_in, const int* in_sizes, int n_in,
                              void* d_out, int out_size) {
    const float* features = (const float*)d_in[0];
    const int*   visible  = (const int*)d_in[1];
    const int*   label    = (const int*)d_in[2];
    const float* memory   = (const float*)d_in[3];
    const float* clutter  = (const float*)d_in[4];
    const int*   lru      = (const int*)d_in[5];

    float* out = (float*)d_out;
    float* out_sim  = out + OUT_SIM_OFF;
    float* out_nsim = out + OUT_NSIM_OFF;
    float* out_mem  = out + OUT_MEM_OFF;
    float* out_cb   = out + OUT_CB_OFF;

    static cudaStream_t s_aux = nullptr;
    static cudaEvent_t  ev_fork = nullptr, ev_join = nullptr;
    if (s_aux == nullptr) {
        cudaStreamCreateWithFlags(&s_aux, cudaStreamNonBlocking);
        cudaEventCreateWithFlags(&ev_fork, cudaEventDisableTiming);
        cudaEventCreateWithFlags(&ev_join, cudaEventDisableTiming);
        cudaFuncSetAttribute(sim_gemm_tf32_kernel,
                             cudaFuncAttributeMaxDynamicSharedMemorySize, GEMM_DSMEM);
    }

    // Fork immediately: aux has no dependency on g_A.
    cudaEventRecord(ev_fork, 0);
    cudaStreamWaitEvent(s_aux, ev_fork, 0);
    aux_kernel<<<128 + 256 + NCLUT_TOT / 256, 256, 0, s_aux>>>(
        features, visible, label, memory, clutter, lru,
        out_nsim, out_mem, out_cb);
    cudaEventRecord(ev_join, s_aux);

    // Main stream: A conversion (GEMM's only dependency), then GEMM.
    a_convert_kernel<<<M_TOT * MESH_DIM / (8 * 256), 256>>>(features);
    sim_gemm_tf32_kernel<<<NTOT / 128, 512, GEMM_DSMEM>>>(memory, clutter, out_sim);

    // Join: main stream waits for aux.
    cudaStreamWaitEvent(0, ev_join, 0);
}